// round 15
// baseline (speedup 1.0000x reference)
#include <cuda_runtime.h>
#include <cstdint>

// Problem shapes (fixed)
#define Bq 8
#define Eq 8
#define Cq 1024
#define Iq 128
#define Oq 256
#define Tq 8192

#define NTHREADS 288                   // 8 consumer warps + 1 producer warp
#define NCONS 256
#define NCTAS 296                      // 2 persistent CTAs per SM
#define NTILES 1024                    // 2 n x 8 m x 64 be;  tile = 128 x 128
#define BK 32
#define NSTAGE 3
#define STAGE_A (128 * BK * 4)         // 16384
#define STAGE_BYTES (2 * STAGE_A)      // 32768 (A + B, both 128 rows)
#define SMEM_BIAS  0
#define SMEM_MBAR  1024                // full[i]=1024+i*16, empty[i]=1032+i*16
#define SMEM_TILES 2048
#define SMEM_TOTAL (SMEM_TILES + NSTAGE * STAGE_BYTES)   // 100352 -> 2 CTAs/SM

// Monotonic arrival counter (never reset; generation = ticket/NCTAS).
__device__ unsigned int g_zero_ctr = 0;

__device__ __forceinline__ uint32_t smem_u32(const void* p) {
    uint32_t a;
    asm("{ .reg .u64 t; cvta.to.shared.u64 t, %1; cvt.u32.u64 %0, t; }"
        : "=r"(a) : "l"(p));
    return a;
}

#define CP_ASYNC16(saddr, gptr) \
    asm volatile("cp.async.cg.shared.global [%0], [%1], 16;" \
                 :: "r"(saddr), "l"(gptr) : "memory")

// .noinc is load-bearing: the default form increments the expected count
// before arriving (net-zero) and can never flip a fixed-count barrier.
#define CP_MBAR_ARRIVE_NOINC(mbar) \
    asm volatile("cp.async.mbarrier.arrive.noinc.shared::cta.b64 [%0];" \
                 :: "r"(mbar) : "memory")

#define MBAR_INIT(mbar, cnt) \
    asm volatile("mbarrier.init.shared.b64 [%0], %1;" \
                 :: "r"(mbar), "r"(cnt) : "memory")

#define MBAR_ARRIVE(mbar) \
    asm volatile("mbarrier.arrive.shared.b64 _, [%0];" :: "r"(mbar) : "memory")

#define MBAR_WAIT(mbar, ph) do {                                              \
    uint32_t _done;                                                           \
    asm volatile("{\n\t.reg .pred p;\n\t"                                     \
        "mbarrier.try_wait.parity.acquire.cta.shared::cta.b64 p, [%1], %2;\n\t"\
        "selp.b32 %0, 1, 0, p;\n\t}"                                          \
        : "=r"(_done) : "r"(mbar), "r"(ph) : "memory");                       \
    if (!_done) {                                                             \
        asm volatile("{\n\t.reg .pred P1;\n\t"                                \
            "WL_%=:\n\t"                                                      \
            "mbarrier.try_wait.parity.acquire.cta.shared::cta.b64 P1, [%0], %1, 0x989680;\n\t" \
            "@P1 bra.uni WD_%=;\n\t"                                          \
            "bra.uni WL_%=;\n\t"                                              \
            "WD_%=:\n\t}"                                                     \
            :: "r"(mbar), "r"(ph) : "memory");                                \
    }                                                                         \
} while (0)

#define LDSM_X4(r0, r1, r2, r3, addr) \
    asm volatile("ldmatrix.sync.aligned.m8n8.x4.shared.b16 {%0,%1,%2,%3}, [%4];" \
                 : "=r"(r0), "=r"(r1), "=r"(r2), "=r"(r3) : "r"(addr))

#define MMA_TF32(c, a, b0, b1) \
    asm volatile("mma.sync.aligned.m16n8k8.row.col.f32.tf32.tf32.f32 " \
                 "{%0,%1,%2,%3}, {%4,%5,%6,%7}, {%8,%9}, {%0,%1,%2,%3};" \
                 : "+f"((c)[0]), "+f"((c)[1]), "+f"((c)[2]), "+f"((c)[3]) \
                 : "r"((a)[0]), "r"((a)[1]), "r"((a)[2]), "r"((a)[3]), \
                   "r"(b0), "r"(b1))

// ---------------------------------------------------------------------------
// Warp-specialized persistent kernel, 2 CTAs/SM, low-traffic 32x64 warp tiles.
// 296 CTAs x 288 threads. Warps 0-7: consumers (4m x 2n, warp tile 32x64,
// tile 128x128 — lowest smem-traffic proven geometry). Warp 8: producer —
// issues ALL cp.asyncs; cp.async.mbarrier.arrive.noinc on full[b] (init 32);
// consumers try_wait full[b] (parity use&1), compute, lane0 arrives empty[b]
// (init 8); producer waits empty[b] before buffer reuse. No __syncthreads
// in the steady loop.
// Zero stores issued early by consumers; fence + monotonic global barrier
// (consumer-only named barrier 10) deferred to first atomic scatter.
// B smem row s holds weight row P(s)=((s>>4)<<4)+((s&7)<<1)+((s>>3)&1)
// -> contiguous per-thread 4-col groups -> red.global.add.v4.f32.
// tf32 round-to-nearest: +0x1000 on raw f32 fragments before MMA.
// Tile t: n_base=(t&1)*128, m0=((t>>1)&7)*128, be=t>>4.
// ---------------------------------------------------------------------------
extern "C" __global__ void __launch_bounds__(NTHREADS, 2)
moe_ws(const float* __restrict__ x,
       const int*   __restrict__ idx,
       const float* __restrict__ gate,
       const float* __restrict__ w,
       const float* __restrict__ bias,
       float* __restrict__ out) {
    extern __shared__ char smem[];
    const uint32_t sbase = smem_u32(smem);
    const int tid  = threadIdx.x;
    const int wid  = tid >> 5;
    const int lane = tid & 31;
    const int cta  = blockIdx.x;

    // mbarrier init
    if (tid == 0) {
        #pragma unroll
        for (int i = 0; i < NSTAGE; i++) {
            MBAR_INIT(sbase + SMEM_MBAR + i * 16,     32u);  // full: 32 producer lanes
            MBAR_INIT(sbase + SMEM_MBAR + i * 16 + 8,  8u);  // empty: 8 consumer warps
        }
    }
    if (tid < 256) reinterpret_cast<float*>(smem + SMEM_BIAS)[tid] = bias[tid];
    __syncthreads();   // the ONLY block-wide barrier

    if (wid == 8) {
        // ================= PRODUCER =================
        const int l3 = lane >> 3;             // 0..3
        const int c4l = lane & 7;
        int c = 0;
        for (int t = cta; t < NTILES; t += NCTAS) {
            const float* xb = x + ((long)(t >> 4) * Cq + ((t >> 1) & 7) * 128) * Iq;
            const float* wb = w + ((long)((t >> 4) & 7) * Oq + (t & 1) * 128) * Iq;
            #pragma unroll
            for (int j = 0; j < 4; j++) {
                const int b = c % 3;
                const int u = c / 3;
                if (c >= NSTAGE) {
                    MBAR_WAIT(sbase + SMEM_MBAR + b * 16 + 8, (uint32_t)((u - 1) & 1));
                }
                const uint32_t aB = sbase + SMEM_TILES + b * STAGE_BYTES;
                const uint32_t bB = aB + STAGE_A;
                // A: 128 rows x 8 c4 = 1024 float4, 32 per lane
                #pragma unroll
                for (int i = 0; i < 32; i++) {
                    int r = i * 4 + l3;
                    uint32_t soff = (uint32_t)(r * 128 + ((c4l ^ (r & 7)) << 4));
                    CP_ASYNC16(aB + soff, xb + r * Iq + j * BK + c4l * 4);
                }
                // B: 128 rows (permuted) x 8 c4 = 1024 float4, 32 per lane
                #pragma unroll
                for (int i = 0; i < 32; i++) {
                    int s = i * 4 + l3;
                    int ps = ((s >> 4) << 4) + ((s & 7) << 1) + ((s >> 3) & 1);
                    uint32_t soff = (uint32_t)(s * 128 + ((c4l ^ (s & 7)) << 4));
                    CP_ASYNC16(bB + soff, wb + ps * Iq + j * BK + c4l * 4);
                }
                CP_MBAR_ARRIVE_NOINC(sbase + SMEM_MBAR + b * 16);
                c++;
            }
        }
        return;
    }

    // ================= CONSUMERS (warps 0-7) =================
    // warp geometry: 4m x 2n, warp tile 32x64 (R8-proven fragment paths)
    const int m_w = (wid >> 1) * 32;
    const int n_w = (wid & 1) * 64;
    const int sub = lane >> 3;
    const int l7  = lane & 7;
    const int a_r[2] = { m_w + (sub & 1) * 8 + l7, m_w + 16 + (sub & 1) * 8 + l7 };
    const int a_kh = sub >> 1;
    const int b_kh = sub & 1;
    int b_n[4];
    #pragma unroll
    for (int jp = 0; jp < 4; jp++) b_n[jp] = n_w + jp * 16 + (sub >> 1) * 8 + l7;
    const int qrow = lane >> 2;
    const int colq = (lane & 3) * 4;

    // Issue zero stores (fire-and-forget; fence deferred)
    {
        float4* o4 = reinterpret_cast<float4*>(out);
        const int n4 = (Bq * Tq * Oq) / 4;
        float4 z = make_float4(0.f, 0.f, 0.f, 0.f);
        for (int i = cta * NCONS + tid; i < n4; i += NCTAS * NCONS)
            o4[i] = z;
    }

    bool waited = false;
    int c = 0;
    for (int t = cta; t < NTILES; t += NCTAS) {
        const int n_base = (t & 1) * 128;
        const int m0     = ((t >> 1) & 7) * 128;
        const int be     = t >> 4;
        const int b_     = be >> 3;

        float g_r[4];
        int   tok_r[4];
        #pragma unroll
        for (int k = 0; k < 4; k++) {
            int r = m_w + k * 8 + qrow;
            g_r[k]   = gate[(long)be * Cq + m0 + r];
            tok_r[k] = idx [(long)be * Cq + m0 + r];
        }

        float acc[2][8][4];
        #pragma unroll
        for (int i = 0; i < 2; i++)
            #pragma unroll
            for (int j = 0; j < 8; j++)
                #pragma unroll
                for (int q = 0; q < 4; q++) acc[i][j][q] = 0.f;

        #pragma unroll
        for (int j = 0; j < 4; j++) {
            const int b = c % 3;
            const int u = c / 3;
            MBAR_WAIT(sbase + SMEM_MBAR + b * 16, (uint32_t)(u & 1));

            const uint32_t aB = sbase + SMEM_TILES + b * STAGE_BYTES;
            const uint32_t bB = aB + STAGE_A;
            #pragma unroll
            for (int kk = 0; kk < 4; kk++) {
                uint32_t Af[2][4], Bf[4][4];
                #pragma unroll
                for (int i = 0; i < 2; i++) {
                    uint32_t chunk = (uint32_t)((kk * 2 + a_kh) ^ l7);
                    LDSM_X4(Af[i][0], Af[i][1], Af[i][2], Af[i][3],
                            aB + a_r[i] * 128 + (chunk << 4));
                }
                #pragma unroll
                for (int jp = 0; jp < 4; jp++) {
                    uint32_t chunk = (uint32_t)((kk * 2 + b_kh) ^ l7);
                    LDSM_X4(Bf[jp][0], Bf[jp][1], Bf[jp][2], Bf[jp][3],
                            bB + b_n[jp] * 128 + (chunk << 4));
                }
                // tf32 round-to-nearest at the truncation boundary
                #pragma unroll
                for (int i = 0; i < 2; i++)
                    #pragma unroll
                    for (int q = 0; q < 4; q++) Af[i][q] += 0x1000u;
                #pragma unroll
                for (int jp = 0; jp < 4; jp++)
                    #pragma unroll
                    for (int q = 0; q < 4; q++) Bf[jp][q] += 0x1000u;
                #pragma unroll
                for (int i = 0; i < 2; i++)
                    #pragma unroll
                    for (int jn = 0; jn < 8; jn++)
                        MMA_TF32(acc[i][jn], Af[i], Bf[jn >> 1][(jn & 1) * 2],
                                 Bf[jn >> 1][(jn & 1) * 2 + 1]);
            }
            // all this warp's smem reads completed (LDSM->MMA scoreboards)
            if (lane == 0) MBAR_ARRIVE(sbase + SMEM_MBAR + b * 16 + 8);
            c++;
        }

        // Before the FIRST scatter: fence zero stores, consumer-only barrier.
        if (!waited) {
            __threadfence();
            asm volatile("bar.sync 10, %0;" :: "n"(NCONS) : "memory");
            if (tid == 0) {
                unsigned tk;
                asm volatile("atom.add.release.gpu.u32 %0, [%1], %2;"
                             : "=r"(tk) : "l"(&g_zero_ctr), "r"(1u) : "memory");
                unsigned bar_target = (tk / NCTAS + 1) * NCTAS;
                unsigned v;
                do {
                    asm volatile("ld.acquire.gpu.u32 %0, [%1];"
                                 : "=r"(v) : "l"(&g_zero_ctr) : "memory");
                } while (v < bar_target);
            }
            asm volatile("bar.sync 10, %0;" :: "n"(NCONS) : "memory");
            waited = true;
        }

        // Epilogue: bias + gate + red.v4 scatter (permuted-B layout)
        const float* bias_s = reinterpret_cast<const float*>(smem + SMEM_BIAS);
        #pragma unroll
        for (int i = 0; i < 2; i++) {
            #pragma unroll
            for (int half = 0; half < 2; half++) {
                const int k = i * 2 + half;
                float g = g_r[k];
                float* orow = out + ((long)b_ * Tq + tok_r[k]) * Oq;
                #pragma unroll
                for (int jj = 0; jj < 4; jj++) {
                    int col = n_base + ((n_w >> 4) + jj) * 16 + colq;
                    float4 bv = *reinterpret_cast<const float4*>(bias_s + col);
                    float v0 = (acc[i][2 * jj + 0][half * 2 + 0] + bv.x) * g;
                    float v1 = (acc[i][2 * jj + 1][half * 2 + 0] + bv.y) * g;
                    float v2 = (acc[i][2 * jj + 0][half * 2 + 1] + bv.z) * g;
                    float v3 = (acc[i][2 * jj + 1][half * 2 + 1] + bv.w) * g;
                    asm volatile("red.global.add.v4.f32 [%0], {%1, %2, %3, %4};"
                                 :: "l"(orow + col), "f"(v0), "f"(v1), "f"(v2), "f"(v3)
                                 : "memory");
                }
            }
        }
    }
}

// ---------------------------------------------------------------------------
// kernel_launch
// Inputs: x_expert f32, expert_indices i32, expert_gate f32, weight f32,
//         bias f32, num_tokens i32 (unused)
// ---------------------------------------------------------------------------
extern "C" void kernel_launch(void* const* d_in, const int* in_sizes, int n_in,
                              void* d_out, int out_size) {
    const float* x    = (const float*)d_in[0];
    const int*   idx  = (const int*)  d_in[1];
    const float* gate = (const float*)d_in[2];
    const float* w    = (const float*)d_in[3];
    const float* bias = (const float*)d_in[4];
    float* out = (float*)d_out;

    cudaFuncSetAttribute(moe_ws,
                         cudaFuncAttributeMaxDynamicSharedMemorySize, SMEM_TOTAL);
    moe_ws<<<NCTAS, NTHREADS, SMEM_TOTAL>>>(x, idx, gate, w, bias, out);
}

// round 16
// speedup vs baseline: 1.2259x; 1.2259x over previous
#include <cuda_runtime.h>
#include <cstdint>

// Problem shapes (fixed)
#define Bq 8
#define Eq 8
#define Cq 1024
#define Iq 128
#define Oq 256
#define Tq 8192

#define NTHREADS 288                   // 8 consumer warps + 1 producer warp
#define NCONS 256
#define NCTAS 296                      // 2 persistent CTAs per SM
#define NTILES 2048                    // 4 n x 8 m x 64 be;  tile = 128 x 64
#define BK 32
#define NSTAGE 4
#define STAGE_A (128 * BK * 4)         // 16384
#define STAGE_Bb (64 * BK * 4)         // 8192
#define STAGE_BYTES (STAGE_A + STAGE_Bb)   // 24576
#define SMEM_BIAS  0
#define SMEM_MBAR  1024                // full[i]=1024+i*16, empty[i]=1032+i*16
#define SMEM_TILES 2048
#define SMEM_TOTAL (SMEM_TILES + NSTAGE * STAGE_BYTES)   // 100352 -> 2 CTAs/SM

// Monotonic arrival counter (never reset; generation = ticket/NCTAS).
__device__ unsigned int g_zero_ctr = 0;

__device__ __forceinline__ uint32_t smem_u32(const void* p) {
    uint32_t a;
    asm("{ .reg .u64 t; cvta.to.shared.u64 t, %1; cvt.u32.u64 %0, t; }"
        : "=r"(a) : "l"(p));
    return a;
}

#define CP_ASYNC16(saddr, gptr) \
    asm volatile("cp.async.cg.shared.global [%0], [%1], 16;" \
                 :: "r"(saddr), "l"(gptr) : "memory")

// .noinc is load-bearing: the default form increments the expected count
// before arriving (net-zero) and can never flip a fixed-count barrier.
#define CP_MBAR_ARRIVE_NOINC(mbar) \
    asm volatile("cp.async.mbarrier.arrive.noinc.shared::cta.b64 [%0];" \
                 :: "r"(mbar) : "memory")

#define MBAR_INIT(mbar, cnt) \
    asm volatile("mbarrier.init.shared.b64 [%0], %1;" \
                 :: "r"(mbar), "r"(cnt) : "memory")

#define MBAR_ARRIVE(mbar) \
    asm volatile("mbarrier.arrive.shared.b64 _, [%0];" :: "r"(mbar) : "memory")

#define MBAR_WAIT(mbar, ph) do {                                              \
    uint32_t _done;                                                           \
    asm volatile("{\n\t.reg .pred p;\n\t"                                     \
        "mbarrier.try_wait.parity.acquire.cta.shared::cta.b64 p, [%1], %2;\n\t"\
        "selp.b32 %0, 1, 0, p;\n\t}"                                          \
        : "=r"(_done) : "r"(mbar), "r"(ph) : "memory");                       \
    if (!_done) {                                                             \
        asm volatile("{\n\t.reg .pred P1;\n\t"                                \
            "WL_%=:\n\t"                                                      \
            "mbarrier.try_wait.parity.acquire.cta.shared::cta.b64 P1, [%0], %1, 0x989680;\n\t" \
            "@P1 bra.uni WD_%=;\n\t"                                          \
            "bra.uni WL_%=;\n\t"                                              \
            "WD_%=:\n\t}"                                                     \
            :: "r"(mbar), "r"(ph) : "memory");                                \
    }                                                                         \
} while (0)

#define LDSM_X4(r0, r1, r2, r3, addr) \
    asm volatile("ldmatrix.sync.aligned.m8n8.x4.shared.b16 {%0,%1,%2,%3}, [%4];" \
                 : "=r"(r0), "=r"(r1), "=r"(r2), "=r"(r3) : "r"(addr))

#define MMA_TF32(c, a, b0, b1) \
    asm volatile("mma.sync.aligned.m16n8k8.row.col.f32.tf32.tf32.f32 " \
                 "{%0,%1,%2,%3}, {%4,%5,%6,%7}, {%8,%9}, {%0,%1,%2,%3};" \
                 : "+f"((c)[0]), "+f"((c)[1]), "+f"((c)[2]), "+f"((c)[3]) \
                 : "r"((a)[0]), "r"((a)[1]), "r"((a)[2]), "r"((a)[3]), \
                   "r"(b0), "r"(b1))

// ---------------------------------------------------------------------------
// Warp-specialized persistent kernel (R14 WIN config + depth-4 ring).
// 296 CTAs x 288 threads, 2 CTAs/SM. Warps 0-7: consumers (4m x 2n, warp
// tile 32x32, tile 128x64 — fits 96 regs without spill). Warp 8: producer —
// issues ALL cp.asyncs; cp.async.mbarrier.arrive.noinc on full[b] (init 32);
// consumers try_wait full[b] (parity use&1), compute, lane0 arrives empty[b]
// (init 8); producer waits empty[b] before buffer reuse. 4 buffers give the
// producer 3 chunks of run-ahead (vs 2) to absorb DRAM latency jitter.
// No __syncthreads in the steady loop.
// Zero stores issued early by consumers; fence + monotonic global barrier
// (consumer-only named barrier 10) deferred to first atomic scatter.
// B smem row s holds weight row P(s)=((s>>4)<<4)+((s&7)<<1)+((s>>3)&1)
// -> contiguous per-thread 4-col groups -> red.global.add.v4.f32.
// tf32 round-to-nearest: +0x1000 on raw f32 fragments before MMA.
// Tile t: n_base=(t&3)*64, m0=((t>>2)&7)*128, be=t>>5.
// ---------------------------------------------------------------------------
extern "C" __global__ void __launch_bounds__(NTHREADS, 2)
moe_ws(const float* __restrict__ x,
       const int*   __restrict__ idx,
       const float* __restrict__ gate,
       const float* __restrict__ w,
       const float* __restrict__ bias,
       float* __restrict__ out) {
    extern __shared__ char smem[];
    const uint32_t sbase = smem_u32(smem);
    const int tid  = threadIdx.x;
    const int wid  = tid >> 5;
    const int lane = tid & 31;
    const int cta  = blockIdx.x;

    // mbarrier init
    if (tid == 0) {
        #pragma unroll
        for (int i = 0; i < NSTAGE; i++) {
            MBAR_INIT(sbase + SMEM_MBAR + i * 16,     32u);  // full: 32 producer lanes
            MBAR_INIT(sbase + SMEM_MBAR + i * 16 + 8,  8u);  // empty: 8 consumer warps
        }
    }
    if (tid < 256) reinterpret_cast<float*>(smem + SMEM_BIAS)[tid] = bias[tid];
    __syncthreads();   // the ONLY block-wide barrier

    if (wid == 8) {
        // ================= PRODUCER =================
        const int l3 = lane >> 3;
        const int c4l = lane & 7;
        int c = 0;
        for (int t = cta; t < NTILES; t += NCTAS) {
            const float* xb = x + ((long)(t >> 5) * Cq + ((t >> 2) & 7) * 128) * Iq;
            const float* wb = w + ((long)((t >> 5) & 7) * Oq + (t & 3) * 64) * Iq;
            #pragma unroll
            for (int j = 0; j < 4; j++) {
                const int b = c & 3;
                const int u = c >> 2;
                if (c >= NSTAGE) {
                    MBAR_WAIT(sbase + SMEM_MBAR + b * 16 + 8, (uint32_t)((u - 1) & 1));
                }
                const uint32_t aB = sbase + SMEM_TILES + b * STAGE_BYTES;
                const uint32_t bB = aB + STAGE_A;
                // A: 128 rows x 8 c4 = 1024 float4, 32 per lane
                #pragma unroll
                for (int i = 0; i < 32; i++) {
                    int r = i * 4 + l3;
                    uint32_t soff = (uint32_t)(r * 128 + ((c4l ^ (r & 7)) << 4));
                    CP_ASYNC16(aB + soff, xb + r * Iq + j * BK + c4l * 4);
                }
                // B: 64 rows (permuted) x 8 c4 = 512 float4, 16 per lane
                #pragma unroll
                for (int i = 0; i < 16; i++) {
                    int s = i * 4 + l3;
                    int ps = ((s >> 4) << 4) + ((s & 7) << 1) + ((s >> 3) & 1);
                    uint32_t soff = (uint32_t)(s * 128 + ((c4l ^ (s & 7)) << 4));
                    CP_ASYNC16(bB + soff, wb + ps * Iq + j * BK + c4l * 4);
                }
                CP_MBAR_ARRIVE_NOINC(sbase + SMEM_MBAR + b * 16);
                c++;
            }
        }
        return;
    }

    // ================= CONSUMERS (warps 0-7) =================
    // warp geometry: 4m x 2n, warp tile 32x32
    const int m_w = (wid >> 1) * 32;
    const int n_w = (wid & 1) * 32;
    const int sub = lane >> 3;
    const int l7  = lane & 7;
    const int a_r[2] = { m_w + (sub & 1) * 8 + l7, m_w + 16 + (sub & 1) * 8 + l7 };
    const int a_kh = sub >> 1;
    const int b_kh = sub & 1;
    const int b_n[2] = { n_w + (sub >> 1) * 8 + l7, n_w + 16 + (sub >> 1) * 8 + l7 };
    const int qrow = lane >> 2;
    const int colq = (lane & 3) * 4;

    // Issue zero stores (fire-and-forget; fence deferred)
    {
        float4* o4 = reinterpret_cast<float4*>(out);
        const int n4 = (Bq * Tq * Oq) / 4;
        float4 z = make_float4(0.f, 0.f, 0.f, 0.f);
        for (int i = cta * NCONS + tid; i < n4; i += NCTAS * NCONS)
            o4[i] = z;
    }

    bool waited = false;
    int c = 0;
    for (int t = cta; t < NTILES; t += NCTAS) {
        const int n_base = (t & 3) * 64;
        const int m0     = ((t >> 2) & 7) * 128;
        const int be     = t >> 5;
        const int b_     = be >> 3;

        float g_r[4];
        int   tok_r[4];
        #pragma unroll
        for (int k = 0; k < 4; k++) {
            int r = m_w + k * 8 + qrow;
            g_r[k]   = gate[(long)be * Cq + m0 + r];
            tok_r[k] = idx [(long)be * Cq + m0 + r];
        }

        float acc[2][4][4];
        #pragma unroll
        for (int i = 0; i < 2; i++)
            #pragma unroll
            for (int j = 0; j < 4; j++)
                #pragma unroll
                for (int q = 0; q < 4; q++) acc[i][j][q] = 0.f;

        #pragma unroll
        for (int j = 0; j < 4; j++) {
            const int b = c & 3;
            const int u = c >> 2;
            MBAR_WAIT(sbase + SMEM_MBAR + b * 16, (uint32_t)(u & 1));

            const uint32_t aB = sbase + SMEM_TILES + b * STAGE_BYTES;
            const uint32_t bB = aB + STAGE_A;
            #pragma unroll
            for (int kk = 0; kk < 4; kk++) {
                uint32_t Af[2][4], Bf[2][4];
                #pragma unroll
                for (int i = 0; i < 2; i++) {
                    uint32_t chunk = (uint32_t)((kk * 2 + a_kh) ^ l7);
                    LDSM_X4(Af[i][0], Af[i][1], Af[i][2], Af[i][3],
                            aB + a_r[i] * 128 + (chunk << 4));
                }
                #pragma unroll
                for (int jp = 0; jp < 2; jp++) {
                    uint32_t chunk = (uint32_t)((kk * 2 + b_kh) ^ l7);
                    LDSM_X4(Bf[jp][0], Bf[jp][1], Bf[jp][2], Bf[jp][3],
                            bB + b_n[jp] * 128 + (chunk << 4));
                }
                // tf32 round-to-nearest at the truncation boundary
                #pragma unroll
                for (int i = 0; i < 2; i++)
                    #pragma unroll
                    for (int q = 0; q < 4; q++) {
                        Af[i][q] += 0x1000u;
                        Bf[i][q] += 0x1000u;
                    }
                #pragma unroll
                for (int i = 0; i < 2; i++)
                    #pragma unroll
                    for (int jn = 0; jn < 4; jn++)
                        MMA_TF32(acc[i][jn], Af[i], Bf[jn >> 1][(jn & 1) * 2],
                                 Bf[jn >> 1][(jn & 1) * 2 + 1]);
            }
            // all this warp's smem reads completed (LDSM->MMA scoreboards)
            if (lane == 0) MBAR_ARRIVE(sbase + SMEM_MBAR + b * 16 + 8);
            c++;
        }

        // Before the FIRST scatter: fence zero stores, consumer-only barrier.
        if (!waited) {
            __threadfence();
            asm volatile("bar.sync 10, %0;" :: "n"(NCONS) : "memory");
            if (tid == 0) {
                unsigned tk;
                asm volatile("atom.add.release.gpu.u32 %0, [%1], %2;"
                             : "=r"(tk) : "l"(&g_zero_ctr), "r"(1u) : "memory");
                unsigned bar_target = (tk / NCTAS + 1) * NCTAS;
                unsigned v;
                do {
                    asm volatile("ld.acquire.gpu.u32 %0, [%1];"
                                 : "=r"(v) : "l"(&g_zero_ctr) : "memory");
                } while (v < bar_target);
            }
            asm volatile("bar.sync 10, %0;" :: "n"(NCONS) : "memory");
            waited = true;
        }

        // Epilogue: bias + gate + red.v4 scatter (permuted-B layout)
        const float* bias_s = reinterpret_cast<const float*>(smem + SMEM_BIAS);
        #pragma unroll
        for (int i = 0; i < 2; i++) {
            #pragma unroll
            for (int half = 0; half < 2; half++) {
                const int k = i * 2 + half;
                float g = g_r[k];
                float* orow = out + ((long)b_ * Tq + tok_r[k]) * Oq;
                #pragma unroll
                for (int jj = 0; jj < 2; jj++) {
                    int col = n_base + ((n_w >> 4) + jj) * 16 + colq;
                    float4 bv = *reinterpret_cast<const float4*>(bias_s + col);
                    float v0 = (acc[i][2 * jj + 0][half * 2 + 0] + bv.x) * g;
                    float v1 = (acc[i][2 * jj + 1][half * 2 + 0] + bv.y) * g;
                    float v2 = (acc[i][2 * jj + 0][half * 2 + 1] + bv.z) * g;
                    float v3 = (acc[i][2 * jj + 1][half * 2 + 1] + bv.w) * g;
                    asm volatile("red.global.add.v4.f32 [%0], {%1, %2, %3, %4};"
                                 :: "l"(orow + col), "f"(v0), "f"(v1), "f"(v2), "f"(v3)
                                 : "memory");
                }
            }
        }
    }
}

// ---------------------------------------------------------------------------
// kernel_launch
// Inputs: x_expert f32, expert_indices i32, expert_gate f32, weight f32,
//         bias f32, num_tokens i32 (unused)
// ---------------------------------------------------------------------------
extern "C" void kernel_launch(void* const* d_in, const int* in_sizes, int n_in,
                              void* d_out, int out_size) {
    const float* x    = (const float*)d_in[0];
    const int*   idx  = (const int*)  d_in[1];
    const float* gate = (const float*)d_in[2];
    const float* w    = (const float*)d_in[3];
    const float* bias = (const float*)d_in[4];
    float* out = (float*)d_out;

    cudaFuncSetAttribute(moe_ws,
                         cudaFuncAttributeMaxDynamicSharedMemorySize, SMEM_TOTAL);
    moe_ws<<<NCTAS, NTHREADS, SMEM_TOTAL>>>(x, idx, gate, w, bias, out);
}